// round 1
// baseline (speedup 1.0000x reference)
#include <cuda_runtime.h>

typedef unsigned long long ull;

// ---- packed f32x2 helpers (FFMA2 is PTX-only; ptxas won't auto-fuse) ----
__device__ __forceinline__ ull pack2(float x) {
    ull r;
    asm("mov.b64 %0, {%1, %1};" : "=l"(r) : "f"(x));
    return r;
}
__device__ __forceinline__ void ffma2(ull &d, ull a, ull b) {
    asm("fma.rn.f32x2 %0, %1, %2, %0;" : "+l"(d) : "l"(a), "l"(b));
}
__device__ __forceinline__ void unpack2(ull v, float &lo, float &hi) {
    asm("mov.b64 {%0, %1}, %2;" : "=f"(lo), "=f"(hi) : "l"(v));
}

// Per node:
//   out0[w]   = 0.01*( C000 * sum_{u,v}   x0[u]   * y0[v]    * w000[u,v,w]
//             +        C110 * sum_{u,v,i} x1[u,i] * y1[v,i]  * w110[u,v,w] )
//   out1[w,k] = 0.01*( C011 * sum_{u,v}   x0[u]   * y1[v,k]  * w011[u,v,w]
//             +        C101 * sum_{u,v}   x1[u,k] * y0[v]    * w101[u,v,w] )
// Strategy: reduce over u first into Z-accumulators (128 fp32 = 64 f32x2 regs),
// combine with y in a tiny epilogue. Weights staged in smem, broadcast LDS.

__global__ void __launch_bounds__(128) fctp_kernel(
    const float* __restrict__ nf, const float* __restrict__ pf,
    const float* __restrict__ w000, const float* __restrict__ w011,
    const float* __restrict__ w101, const float* __restrict__ w110,
    float* __restrict__ out, int n)
{
    // per u: [w000 16][w011 16][w110 16][w101 16] floats = 32 ull. Total 32 KB.
    __shared__ ull Wsh[128 * 32];
    float* WshF = reinterpret_cast<float*>(Wsh);
    const int tid = threadIdx.x;
    for (int idx = tid; idx < 2048; idx += 128) {
        int u = idx >> 4, j = idx & 15;
        WshF[u * 64 +      j] = w000[idx];
        WshF[u * 64 + 16 + j] = w011[idx];
        WshF[u * 64 + 32 + j] = w110[idx];
        WshF[u * 64 + 48 + j] = w101[idx];
    }
    __syncthreads();

    const int node = blockIdx.x * 128 + tid;
    if (node >= n) return;

    // y: y0[v] = y[v], y1[v][i] = y[4 + 3v + i]
    float y[16];
    {
        const float4* p4 = reinterpret_cast<const float4*>(pf + (size_t)node * 16);
        #pragma unroll
        for (int q = 0; q < 4; q++) {
            float4 t = p4[q];
            y[4*q+0] = t.x; y[4*q+1] = t.y; y[4*q+2] = t.z; y[4*q+3] = t.w;
        }
    }

    // Accumulators: flattened (v*4+w) pairs. 64 ull = 128 fp32 regs.
    ull z000[8], z011[8], z110[3][8], z101[3][8];
    #pragma unroll
    for (int p = 0; p < 8; p++) {
        z000[p] = 0ull; z011[p] = 0ull;
        z110[0][p] = 0ull; z110[1][p] = 0ull; z110[2][p] = 0ull;
        z101[0][p] = 0ull; z101[1][p] = 0ull; z101[2][p] = 0ull;
    }

    const float4* x0v = reinterpret_cast<const float4*>(nf + (size_t)node * 512);
    const float4* x1v = x0v + 32;  // x1 starts at float offset 128

    for (int uc = 0; uc < 32; uc++) {  // 4 u's per iteration
        float4 a  = x0v[uc];
        float4 b0 = x1v[3*uc + 0];
        float4 b1 = x1v[3*uc + 1];
        float4 b2 = x1v[3*uc + 2];
        float x0s[4]    = { a.x, a.y, a.z, a.w };
        float x1s[4][3] = { {b0.x, b0.y, b0.z},
                            {b0.w, b1.x, b1.y},
                            {b1.z, b1.w, b2.x},
                            {b2.y, b2.z, b2.w} };
        #pragma unroll
        for (int j = 0; j < 4; j++) {
            const ulonglong2* wp =
                reinterpret_cast<const ulonglong2*>(Wsh + (4*uc + j) * 32);
            ull xa = pack2(x0s[j]);
            ull xb0 = pack2(x1s[j][0]);
            ull xb1 = pack2(x1s[j][1]);
            ull xb2 = pack2(x1s[j][2]);
            #pragma unroll
            for (int p = 0; p < 4; p++) {           // w000 with x0
                ulonglong2 w = wp[p];
                ffma2(z000[2*p],   xa, w.x);
                ffma2(z000[2*p+1], xa, w.y);
            }
            #pragma unroll
            for (int p = 0; p < 4; p++) {           // w011 with x0
                ulonglong2 w = wp[4 + p];
                ffma2(z011[2*p],   xa, w.x);
                ffma2(z011[2*p+1], xa, w.y);
            }
            #pragma unroll
            for (int p = 0; p < 4; p++) {           // w110 with x1[u,i], i=0..2
                ulonglong2 w = wp[8 + p];
                ffma2(z110[0][2*p],   xb0, w.x);
                ffma2(z110[0][2*p+1], xb0, w.y);
                ffma2(z110[1][2*p],   xb1, w.x);
                ffma2(z110[1][2*p+1], xb1, w.y);
                ffma2(z110[2][2*p],   xb2, w.x);
                ffma2(z110[2][2*p+1], xb2, w.y);
            }
            #pragma unroll
            for (int p = 0; p < 4; p++) {           // w101 with x1[u,k], k=0..2
                ulonglong2 w = wp[12 + p];
                ffma2(z101[0][2*p],   xb0, w.x);
                ffma2(z101[0][2*p+1], xb0, w.y);
                ffma2(z101[1][2*p],   xb1, w.x);
                ffma2(z101[1][2*p+1], xb1, w.y);
                ffma2(z101[2][2*p],   xb2, w.x);
                ffma2(z101[2][2*p+1], xb2, w.y);
            }
        }
    }

    // Unpack accumulators
    float f000[16], f011[16], f110[3][16], f101[3][16];
    #pragma unroll
    for (int p = 0; p < 8; p++) {
        unpack2(z000[p], f000[2*p], f000[2*p+1]);
        unpack2(z011[p], f011[2*p], f011[2*p+1]);
        #pragma unroll
        for (int i = 0; i < 3; i++) {
            unpack2(z110[i][p], f110[i][2*p], f110[i][2*p+1]);
            unpack2(z101[i][p], f101[i][2*p], f101[i][2*p+1]);
        }
    }

    // 0.01 * C folded in
    const float c000 = 3.125e-4f;                 // 0.01 / 32
    const float c110 = 1.8042195912175807e-4f;    // 0.01 / (32*sqrt(3))
    const float c011 = 3.125e-4f;
    const float c101 = 3.125e-4f;

    float o0[4], o1[4][3];
    #pragma unroll
    for (int w = 0; w < 4; w++) {
        float s = 0.f, t = 0.f;
        #pragma unroll
        for (int v = 0; v < 4; v++) {
            s += f000[v*4 + w] * y[v];
            #pragma unroll
            for (int i = 0; i < 3; i++)
                t += f110[i][v*4 + w] * y[4 + 3*v + i];
        }
        o0[w] = c000 * s + c110 * t;
    }
    #pragma unroll
    for (int w = 0; w < 4; w++) {
        #pragma unroll
        for (int k = 0; k < 3; k++) {
            float s = 0.f, t = 0.f;
            #pragma unroll
            for (int v = 0; v < 4; v++) {
                s += f011[v*4 + w]    * y[4 + 3*v + k];
                t += f101[k][v*4 + w] * y[v];
            }
            o1[w][k] = c011 * s + c101 * t;
        }
    }
    o0[0] = 0.0f;  // reference zeroes column 0

    float4* o4 = reinterpret_cast<float4*>(out + (size_t)node * 16);
    o4[0] = make_float4(o0[0],    o0[1],    o0[2],    o0[3]);
    o4[1] = make_float4(o1[0][0], o1[0][1], o1[0][2], o1[1][0]);
    o4[2] = make_float4(o1[1][1], o1[1][2], o1[2][0], o1[2][1]);
    o4[3] = make_float4(o1[2][2], o1[3][0], o1[3][1], o1[3][2]);
}

extern "C" void kernel_launch(void* const* d_in, const int* in_sizes, int n_in,
                              void* d_out, int out_size) {
    const float* nf   = (const float*)d_in[0];  // node_feat (N,512)
    const float* pf   = (const float*)d_in[1];  // pot_feat  (N,16)
    const float* w000 = (const float*)d_in[2];
    const float* w011 = (const float*)d_in[3];
    const float* w101 = (const float*)d_in[4];
    const float* w110 = (const float*)d_in[5];
    float* out = (float*)d_out;
    int n = in_sizes[0] / 512;
    int blocks = (n + 127) / 128;
    fctp_kernel<<<blocks, 128>>>(nf, pf, w000, w011, w101, w110, out, n);
}

// round 2
// speedup vs baseline: 1.0601x; 1.0601x over previous
#include <cuda_runtime.h>

typedef unsigned long long ull;

__device__ __forceinline__ ull pack2(float x) {
    ull r; asm("mov.b64 %0, {%1, %1};" : "=l"(r) : "f"(x)); return r;
}
__device__ __forceinline__ void ffma2(ull &d, ull a, ull b) {
    asm("fma.rn.f32x2 %0, %1, %2, %0;" : "+l"(d) : "l"(a), "l"(b));
}
__device__ __forceinline__ void unpack2(ull v, float &lo, float &hi) {
    asm("mov.b64 {%0, %1}, %2;" : "=f"(lo), "=f"(hi) : "l"(v));
}

// ---- layout constants (floats) ----
#define W_STRIDE 2056            // 2048 + 8 pad → weight LDS.128 conflict-free (2 wf)
#define XS_PITCH 34              // per-xt row: 32 nodes + 2 pad (keeps 8B align + distinct banks)
#define XS_SIZE  (8 * 4 * XS_PITCH)   // 8 u's × 4 xtypes × 34 = 1088
#define ZB_PITCH 132             // per-node row of 128 cols + 4 pad (16B-aligned rows)
#define ZB_SIZE  (16 * ZB_PITCH) // 16-node epilogue batch = 2112
#define SMEM_FLOATS (4*W_STRIDE + 4*XS_SIZE + 4*ZB_SIZE)   // 8224+4352+8448 = 21024
#define SMEM_BYTES  (SMEM_FLOATS * 4)                      // 84096

// Column map: col = w*32 + g*4 + v
//   g0: Z000 (x0, w000)   g1: Z011 (x0, w011)
//   g2..4: Z110[i=g-2] (x1[:,i], w110)   g5..7: Z101[k=g-5] (x1[:,k], w101)
// Warp tile: 32 nodes; lane owns (g=lane>>2, v=lane&3), all 4 w, all 32 nodes.

__global__ void __launch_bounds__(128, 2) fctp_main(
    const float* __restrict__ nf, const float* __restrict__ pf,
    const float* __restrict__ w000, const float* __restrict__ w011,
    const float* __restrict__ w101, const float* __restrict__ w110,
    float* __restrict__ out)
{
    extern __shared__ float S[];
    float* Wm = S;
    const int tid  = threadIdx.x;
    const int warp = tid >> 5, lane = tid & 31;

    // Stage weights with 0.01*C folded in. t: 0=w000 1=w011 2=w110 3=w101
    {
        const float c000 = 3.125e-4f;                // 0.01/32
        const float c110 = 1.8042195912175807e-4f;   // 0.01/(32*sqrt(3))
        for (int i = tid; i < 2048; i += 128) {
            Wm[0*W_STRIDE + i] = c000 * w000[i];
            Wm[1*W_STRIDE + i] = c000 * w011[i];
            Wm[2*W_STRIDE + i] = c110 * w110[i];
            Wm[3*W_STRIDE + i] = c000 * w101[i];
        }
    }
    __syncthreads();

    float* XSw = S + 4*W_STRIDE + warp * XS_SIZE;
    float* ZBw = S + 4*W_STRIDE + 4*XS_SIZE + warp * ZB_SIZE;

    const int g = lane >> 2, v = lane & 3;
    const int t  = (g == 0) ? 0 : (g == 1) ? 1 : (g <= 4) ? 2 : 3;
    const int xt = (g <= 1) ? 0 : (g <= 4) ? (g - 1) : (g - 4);
    const float* Wrow   = Wm + t * W_STRIDE + v * 4;
    const float* xbase0 = XSw + XS_PITCH * xt;

    const int nodeBase = blockIdx.x * 128 + warp * 32;
    const float* nfp = nf + (size_t)(nodeBase + lane) * 512;

    ull acc[4][16];
    #pragma unroll
    for (int c = 0; c < 4; c++)
        #pragma unroll
        for (int j = 0; j < 16; j++) acc[c][j] = 0ull;

    // chunk registers (8 u's of x for my node): x0 8 floats, x1 24 floats
    float4 a0[2], a1[6];
    {
        const float4* p0 = (const float4*)(nfp);
        const float4* p1 = (const float4*)(nfp + 128);
        a0[0] = p0[0]; a0[1] = p0[1];
        #pragma unroll
        for (int k = 0; k < 6; k++) a1[k] = p1[k];
    }

    for (int c = 0; c < 16; c++) {
        // ---- stage chunk into XS (type-major, node index = lane) ----
        const float* f0 = (const float*)a0;
        const float* f1 = (const float*)a1;
        #pragma unroll
        for (int up = 0; up < 8; up++) {
            XSw[136*up /*8*XS_PITCH*4? no: up*(4*XS_PITCH)*/ ] = 0.0f; // placeholder removed below
        }
        // NOTE: XS layout idx = up*(4*XS_PITCH) + xtSlot*XS_PITCH + node
        #pragma unroll
        for (int up = 0; up < 8; up++) {
            float* row = XSw + up * (4 * XS_PITCH);
            row[lane] = f0[up];                       // xt slot 0 (x0)
            row[XS_PITCH     + lane] = f1[3*up + 0];  // x1 comp 0
            row[2*XS_PITCH   + lane] = f1[3*up + 1];  // x1 comp 1
            row[3*XS_PITCH   + lane] = f1[3*up + 2];  // x1 comp 2
        }
        __syncwarp();

        // ---- prefetch next chunk while computing ----
        if (c < 15) {
            const float4* p0 = (const float4*)(nfp + 8*(c+1));
            const float4* p1 = (const float4*)(nfp + 128 + 24*(c+1));
            a0[0] = p0[0]; a0[1] = p0[1];
            #pragma unroll
            for (int k = 0; k < 6; k++) a1[k] = p1[k];
        }

        // ---- compute 8 u's over 32 nodes ----
        #pragma unroll
        for (int up = 0; up < 8; up++) {
            const int wrow = c * 8 + up;
            float4 wv = *(const float4*)(Wrow + wrow * 16);
            ull wd0 = pack2(wv.x), wd1 = pack2(wv.y),
                wd2 = pack2(wv.z), wd3 = pack2(wv.w);
            const float* xb = xbase0 + up * (4 * XS_PITCH);
            #pragma unroll
            for (int jp = 0; jp < 16; jp++) {
                ull xp = *(const ull*)(xb + 2*jp);
                ffma2(acc[0][jp], xp, wd0);
                ffma2(acc[1][jp], xp, wd1);
                ffma2(acc[2][jp], xp, wd2);
                ffma2(acc[3][jp], xp, wd3);
            }
        }
        __syncwarp();   // before overwriting XS next chunk
    }

    // ================= epilogue: two 16-node batches =================
    const int ndl = lane >> 1;       // node within batch (2 lanes per node)
    const int h   = lane & 1;        // which pair of w's this lane handles

    #pragma unroll
    for (int b = 0; b < 2; b++) {
        // scatter my acc (cols w*32 + g*4 + v ≡ w*32 + lane) for nodes of this batch
        #pragma unroll
        for (int cc = 0; cc < 4; cc++) {
            #pragma unroll
            for (int p = 0; p < 8; p++) {
                float lo, hi;
                unpack2(acc[cc][b*8 + p], lo, hi);
                ZBw[(2*p    ) * ZB_PITCH + cc*32 + lane] = lo;
                ZBw[(2*p + 1) * ZB_PITCH + cc*32 + lane] = hi;
            }
        }
        __syncwarp();

        const int node = nodeBase + b*16 + ndl;
        const float4* pf4 = (const float4*)(pf + (size_t)node * 16);
        float4 q0 = pf4[0], q1 = pf4[1], q2 = pf4[2], q3 = pf4[3];
        float y0v[4]  = { q0.x, q0.y, q0.z, q0.w };
        float yy[12]  = { q1.x, q1.y, q1.z, q1.w,     // yy[3v+i] = y1[v][i]
                          q2.x, q2.y, q2.z, q2.w,
                          q3.x, q3.y, q3.z, q3.w };

        const float4* Z4 = (const float4*)(ZBw + ndl * ZB_PITCH);
        float o0[2], o1[2][3];
        #pragma unroll
        for (int ww = 0; ww < 2; ww++) {
            const int w = 2*h + ww;
            const float4* Zw = Z4 + w * 8;
            float4 z000 = Zw[0], z011 = Zw[1];
            float4 z110a = Zw[2], z110b = Zw[3], z110c = Zw[4];
            float4 z101a = Zw[5], z101b = Zw[6], z101c = Zw[7];

            float s = z000.x*y0v[0] + z000.y*y0v[1] + z000.z*y0v[2] + z000.w*y0v[3];
            s += z110a.x*yy[0] + z110a.y*yy[3] + z110a.z*yy[6] + z110a.w*yy[9];
            s += z110b.x*yy[1] + z110b.y*yy[4] + z110b.z*yy[7] + z110b.w*yy[10];
            s += z110c.x*yy[2] + z110c.y*yy[5] + z110c.z*yy[8] + z110c.w*yy[11];
            o0[ww] = s;

            o1[ww][0] = z011.x*yy[0] + z011.y*yy[3] + z011.z*yy[6] + z011.w*yy[9]
                      + z101a.x*y0v[0] + z101a.y*y0v[1] + z101a.z*y0v[2] + z101a.w*y0v[3];
            o1[ww][1] = z011.x*yy[1] + z011.y*yy[4] + z011.z*yy[7] + z011.w*yy[10]
                      + z101b.x*y0v[0] + z101b.y*y0v[1] + z101b.z*y0v[2] + z101b.w*y0v[3];
            o1[ww][2] = z011.x*yy[2] + z011.y*yy[5] + z011.z*yy[8] + z011.w*yy[11]
                      + z101c.x*y0v[0] + z101c.y*y0v[1] + z101c.z*y0v[2] + z101c.w*y0v[3];
        }
        if (h == 0) o0[0] = 0.0f;   // reference zeroes out[:,0]

        float* op = out + (size_t)node * 16;
        // out0[w] at [w]; out1[w][k] at [4 + 3w + k]
        op[2*h    ] = o0[0];
        op[2*h + 1] = o0[1];
        float* o1p = op + 4 + 6*h;   // h=0 → floats 4..9 (w=0,1); h=1 → 10..15 (w=2,3)
        o1p[0] = o1[0][0]; o1p[1] = o1[0][1]; o1p[2] = o1[0][2];
        o1p[3] = o1[1][0]; o1p[4] = o1[1][1]; o1p[5] = o1[1][2];

        __syncwarp();
    }
}

// naive tail kernel (only runs if n % 128 != 0; negligible work)
__global__ void fctp_tail(
    const float* __restrict__ nf, const float* __restrict__ pf,
    const float* __restrict__ w000, const float* __restrict__ w011,
    const float* __restrict__ w101, const float* __restrict__ w110,
    float* __restrict__ out, int start, int n)
{
    int node = start + blockIdx.x * blockDim.x + threadIdx.x;
    if (node >= n) return;
    const float* x = nf + (size_t)node * 512;
    const float* y = pf + (size_t)node * 16;
    float y0v[4], y1v[4][3];
    for (int v0 = 0; v0 < 4; v0++) {
        y0v[v0] = y[v0];
        for (int i = 0; i < 3; i++) y1v[v0][i] = y[4 + 3*v0 + i];
    }
    float o0[4] = {0,0,0,0}, o1[4][3] = {};
    for (int u = 0; u < 128; u++) {
        float x0u = x[u];
        float x1u[3] = { x[128 + 3*u], x[128 + 3*u + 1], x[128 + 3*u + 2] };
        for (int v0 = 0; v0 < 4; v0++) {
            float s110 = x1u[0]*y1v[v0][0] + x1u[1]*y1v[v0][1] + x1u[2]*y1v[v0][2];
            float xy0 = x0u * y0v[v0];
            for (int w = 0; w < 4; w++) {
                int idx = u*16 + v0*4 + w;
                o0[w] += 3.125e-4f * xy0 * w000[idx]
                       + 1.8042195912175807e-4f * s110 * w110[idx];
                for (int k = 0; k < 3; k++)
                    o1[w][k] += 3.125e-4f * (x0u * y1v[v0][k] * w011[idx]
                                           + x1u[k] * y0v[v0] * w101[idx]);
            }
        }
    }
    o0[0] = 0.0f;
    float* op = out + (size_t)node * 16;
    for (int w = 0; w < 4; w++) op[w] = o0[w];
    for (int w = 0; w < 4; w++)
        for (int k = 0; k < 3; k++) op[4 + 3*w + k] = o1[w][k];
}

extern "C" void kernel_launch(void* const* d_in, const int* in_sizes, int n_in,
                              void* d_out, int out_size) {
    const float* nf   = (const float*)d_in[0];
    const float* pf   = (const float*)d_in[1];
    const float* w000 = (const float*)d_in[2];
    const float* w011 = (const float*)d_in[3];
    const float* w101 = (const float*)d_in[4];
    const float* w110 = (const float*)d_in[5];
    float* out = (float*)d_out;
    int n = in_sizes[0] / 512;
    int nb  = n >> 7;
    int rem = n & 127;
    cudaFuncSetAttribute(fctp_main, cudaFuncAttributeMaxDynamicSharedMemorySize, SMEM_BYTES);
    if (nb > 0)
        fctp_main<<<nb, 128, SMEM_BYTES>>>(nf, pf, w000, w011, w101, w110, out);
    if (rem > 0)
        fctp_tail<<<1, 128>>>(nf, pf, w000, w011, w101, w110, out, nb * 128, n);
}

// round 3
// speedup vs baseline: 1.0734x; 1.0125x over previous
#include <cuda_runtime.h>

typedef unsigned long long ull;

__device__ __forceinline__ ull pack2(float x) {
    ull r; asm("mov.b64 %0, {%1, %1};" : "=l"(r) : "f"(x)); return r;
}
__device__ __forceinline__ void ffma2(ull &d, ull a, ull b) {
    asm("fma.rn.f32x2 %0, %1, %2, %0;" : "+l"(d) : "l"(a), "l"(b));
}
__device__ __forceinline__ void unpack2(ull v, float &lo, float &hi) {
    asm("mov.b64 {%0, %1}, %2;" : "=f"(lo), "=f"(hi) : "l"(v));
}

// ---- layout constants (floats) ----
#define W_STRIDE 2056        // 2048+8: 16 distinct LDS.128 addrs balance into 2 phases (2 wf)
#define XS_PITCH 36          // 32 nodes + 4 pad; 144B rows: 16B-aligned, distinct bank groups
#define XS_UPSTRIDE (4 * XS_PITCH)       // 144 floats per u
#define XS_SIZE  (8 * XS_UPSTRIDE)       // 1152 floats (8 u's staged per chunk)
#define ZB_PITCH 132                     // per-node row: 128 cols + 4 pad (16B-aligned)
#define ZB_SIZE  (16 * ZB_PITCH)         // 2112 floats (16-node epilogue batch)
#define SCRATCH  ZB_SIZE                 // per-warp scratch = max(XS_SIZE, ZB_SIZE) = 2112
#define SMEM_FLOATS (4*W_STRIDE + 4*SCRATCH)   // 8224 + 8448 = 16672
#define SMEM_BYTES  (SMEM_FLOATS * 4)          // 66688

// Column map: col = w*32 + g*4 + v
//   g0: Z000 (x0, w000)   g1: Z011 (x0, w011)
//   g2..4: Z110[i=g-2] (x1[:,i], w110)   g5..7: Z101[k=g-5] (x1[:,k], w101)
// Warp tile: 32 nodes; lane owns (g=lane>>2, v=lane&3), all 4 w, all 32 nodes.

__global__ void __launch_bounds__(128, 2) fctp_main(
    const float* __restrict__ nf, const float* __restrict__ pf,
    const float* __restrict__ w000, const float* __restrict__ w011,
    const float* __restrict__ w101, const float* __restrict__ w110,
    float* __restrict__ out)
{
    extern __shared__ float S[];
    float* Wm = S;
    const int tid  = threadIdx.x;
    const int warp = tid >> 5, lane = tid & 31;

    // Stage weights with 0.01*C folded in. t: 0=w000 1=w011 2=w110 3=w101
    {
        const float c000 = 3.125e-4f;                // 0.01/32
        const float c110 = 1.8042195912175807e-4f;   // 0.01/(32*sqrt(3))
        for (int i = tid; i < 2048; i += 128) {
            Wm[0*W_STRIDE + i] = c000 * w000[i];
            Wm[1*W_STRIDE + i] = c000 * w011[i];
            Wm[2*W_STRIDE + i] = c110 * w110[i];
            Wm[3*W_STRIDE + i] = c000 * w101[i];
        }
    }
    __syncthreads();

    float* XSw = S + 4*W_STRIDE + warp * SCRATCH;   // x staging (loop phase)
    float* ZBw = XSw;                               // epilogue scratch (same region)

    const int g = lane >> 2, v = lane & 3;
    const int t  = (g == 0) ? 0 : (g == 1) ? 1 : (g <= 4) ? 2 : 3;
    const int xt = (g <= 1) ? 0 : (g <= 4) ? (g - 1) : (g - 4);
    const float* Wrow   = Wm + t * W_STRIDE + v * 4;
    const float* xbase0 = XSw + XS_PITCH * xt;

    const int nodeBase = blockIdx.x * 128 + warp * 32;
    const float* nfp = nf + (size_t)(nodeBase + lane) * 512;

    ull acc[4][16];
    #pragma unroll
    for (int c = 0; c < 4; c++)
        #pragma unroll
        for (int j = 0; j < 16; j++) acc[c][j] = 0ull;

    // chunk registers (8 u's of x for my node): x0 8 floats, x1 24 floats
    float4 a0[2], a1[6];
    {
        const float4* p0 = (const float4*)(nfp);
        const float4* p1 = (const float4*)(nfp + 128);
        a0[0] = p0[0]; a0[1] = p0[1];
        #pragma unroll
        for (int k = 0; k < 6; k++) a1[k] = p1[k];
    }

    for (int c = 0; c < 16; c++) {
        // ---- stage chunk into XS: idx = up*XS_UPSTRIDE + xt*XS_PITCH + node ----
        const float* f0 = (const float*)a0;
        const float* f1 = (const float*)a1;
        #pragma unroll
        for (int up = 0; up < 8; up++) {
            float* row = XSw + up * XS_UPSTRIDE;
            row[lane]               = f0[up];         // x0
            row[XS_PITCH   + lane]  = f1[3*up + 0];   // x1 comp 0
            row[2*XS_PITCH + lane]  = f1[3*up + 1];   // x1 comp 1
            row[3*XS_PITCH + lane]  = f1[3*up + 2];   // x1 comp 2
        }
        __syncwarp();

        // ---- prefetch next chunk while computing ----
        if (c < 15) {
            const float4* p0 = (const float4*)(nfp + 8*(c+1));
            const float4* p1 = (const float4*)(nfp + 128 + 24*(c+1));
            a0[0] = p0[0]; a0[1] = p0[1];
            #pragma unroll
            for (int k = 0; k < 6; k++) a1[k] = p1[k];
        }

        // ---- compute 8 u's over 32 nodes ----
        #pragma unroll
        for (int up = 0; up < 8; up++) {
            float4 wv = *(const float4*)(Wrow + (c*8 + up) * 16);
            ull wd0 = pack2(wv.x), wd1 = pack2(wv.y),
                wd2 = pack2(wv.z), wd3 = pack2(wv.w);
            const float* xb = xbase0 + up * XS_UPSTRIDE;
            #pragma unroll
            for (int q = 0; q < 8; q++) {             // 4 nodes per LDS.128
                ulonglong2 xq = *(const ulonglong2*)(xb + 4*q);
                ffma2(acc[0][2*q],   xq.x, wd0);
                ffma2(acc[0][2*q+1], xq.y, wd0);
                ffma2(acc[1][2*q],   xq.x, wd1);
                ffma2(acc[1][2*q+1], xq.y, wd1);
                ffma2(acc[2][2*q],   xq.x, wd2);
                ffma2(acc[2][2*q+1], xq.y, wd2);
                ffma2(acc[3][2*q],   xq.x, wd3);
                ffma2(acc[3][2*q+1], xq.y, wd3);
            }
        }
        __syncwarp();   // XS reused next chunk (and by epilogue)
    }

    // ================= epilogue: two 16-node batches =================
    const int ndl = lane >> 1;       // node within batch (2 lanes per node)
    const int h   = lane & 1;        // which pair of w's this lane handles

    #pragma unroll
    for (int b = 0; b < 2; b++) {
        // scatter my acc (cols w*32 + g*4 + v == w*32 + lane) for this batch
        #pragma unroll
        for (int cc = 0; cc < 4; cc++) {
            #pragma unroll
            for (int p = 0; p < 8; p++) {
                float lo, hi;
                unpack2(acc[cc][b*8 + p], lo, hi);
                ZBw[(2*p    ) * ZB_PITCH + cc*32 + lane] = lo;
                ZBw[(2*p + 1) * ZB_PITCH + cc*32 + lane] = hi;
            }
        }
        __syncwarp();

        const int node = nodeBase + b*16 + ndl;
        const float4* pf4 = (const float4*)(pf + (size_t)node * 16);
        float4 q0 = pf4[0], q1 = pf4[1], q2 = pf4[2], q3 = pf4[3];
        float y0v[4]  = { q0.x, q0.y, q0.z, q0.w };
        float yy[12]  = { q1.x, q1.y, q1.z, q1.w,     // yy[3v+i] = y1[v][i]
                          q2.x, q2.y, q2.z, q2.w,
                          q3.x, q3.y, q3.z, q3.w };

        const float4* Z4 = (const float4*)(ZBw + ndl * ZB_PITCH);
        float o0[2], o1[2][3];
        #pragma unroll
        for (int ww = 0; ww < 2; ww++) {
            const int w = 2*h + ww;
            const float4* Zw = Z4 + w * 8;
            float4 z000 = Zw[0], z011 = Zw[1];
            float4 z110a = Zw[2], z110b = Zw[3], z110c = Zw[4];
            float4 z101a = Zw[5], z101b = Zw[6], z101c = Zw[7];

            float s = z000.x*y0v[0] + z000.y*y0v[1] + z000.z*y0v[2] + z000.w*y0v[3];
            s += z110a.x*yy[0] + z110a.y*yy[3] + z110a.z*yy[6] + z110a.w*yy[9];
            s += z110b.x*yy[1] + z110b.y*yy[4] + z110b.z*yy[7] + z110b.w*yy[10];
            s += z110c.x*yy[2] + z110c.y*yy[5] + z110c.z*yy[8] + z110c.w*yy[11];
            o0[ww] = s;

            o1[ww][0] = z011.x*yy[0] + z011.y*yy[3] + z011.z*yy[6] + z011.w*yy[9]
                      + z101a.x*y0v[0] + z101a.y*y0v[1] + z101a.z*y0v[2] + z101a.w*y0v[3];
            o1[ww][1] = z011.x*yy[1] + z011.y*yy[4] + z011.z*yy[7] + z011.w*yy[10]
                      + z101b.x*y0v[0] + z101b.y*y0v[1] + z101b.z*y0v[2] + z101b.w*y0v[3];
            o1[ww][2] = z011.x*yy[2] + z011.y*yy[5] + z011.z*yy[8] + z011.w*yy[11]
                      + z101c.x*y0v[0] + z101c.y*y0v[1] + z101c.z*y0v[2] + z101c.w*y0v[3];
        }
        if (h == 0) o0[0] = 0.0f;   // reference zeroes out[:,0]

        float* op = out + (size_t)node * 16;
        op[2*h    ] = o0[0];
        op[2*h + 1] = o0[1];
        float* o1p = op + 4 + 6*h;
        o1p[0] = o1[0][0]; o1p[1] = o1[0][1]; o1p[2] = o1[0][2];
        o1p[3] = o1[1][0]; o1p[4] = o1[1][1]; o1p[5] = o1[1][2];

        __syncwarp();
    }
}

// naive tail kernel (only runs if n % 128 != 0; negligible work)
__global__ void fctp_tail(
    const float* __restrict__ nf, const float* __restrict__ pf,
    const float* __restrict__ w000, const float* __restrict__ w011,
    const float* __restrict__ w101, const float* __restrict__ w110,
    float* __restrict__ out, int start, int n)
{
    int node = start + blockIdx.x * blockDim.x + threadIdx.x;
    if (node >= n) return;
    const float* x = nf + (size_t)node * 512;
    const float* y = pf + (size_t)node * 16;
    float y0v[4], y1v[4][3];
    for (int v0 = 0; v0 < 4; v0++) {
        y0v[v0] = y[v0];
        for (int i = 0; i < 3; i++) y1v[v0][i] = y[4 + 3*v0 + i];
    }
    float o0[4] = {0,0,0,0}, o1[4][3] = {};
    for (int u = 0; u < 128; u++) {
        float x0u = x[u];
        float x1u[3] = { x[128 + 3*u], x[128 + 3*u + 1], x[128 + 3*u + 2] };
        for (int v0 = 0; v0 < 4; v0++) {
            float s110 = x1u[0]*y1v[v0][0] + x1u[1]*y1v[v0][1] + x1u[2]*y1v[v0][2];
            float xy0 = x0u * y0v[v0];
            for (int w = 0; w < 4; w++) {
                int idx = u*16 + v0*4 + w;
                o0[w] += 3.125e-4f * xy0 * w000[idx]
                       + 1.8042195912175807e-4f * s110 * w110[idx];
                for (int k = 0; k < 3; k++)
                    o1[w][k] += 3.125e-4f * (x0u * y1v[v0][k] * w011[idx]
                                           + x1u[k] * y0v[v0] * w101[idx]);
            }
        }
    }
    o0[0] = 0.0f;
    float* op = out + (size_t)node * 16;
    for (int w = 0; w < 4; w++) op[w] = o0[w];
    for (int w = 0; w < 4; w++)
        for (int k = 0; k < 3; k++) op[4 + 3*w + k] = o1[w][k];
}

extern "C" void kernel_launch(void* const* d_in, const int* in_sizes, int n_in,
                              void* d_out, int out_size) {
    const float* nf   = (const float*)d_in[0];
    const float* pf   = (const float*)d_in[1];
    const float* w000 = (const float*)d_in[2];
    const float* w011 = (const float*)d_in[3];
    const float* w101 = (const float*)d_in[4];
    const float* w110 = (const float*)d_in[5];
    float* out = (float*)d_out;
    int n = in_sizes[0] / 512;
    int nb  = n >> 7;
    int rem = n & 127;
    cudaFuncSetAttribute(fctp_main, cudaFuncAttributeMaxDynamicSharedMemorySize, SMEM_BYTES);
    if (nb > 0)
        fctp_main<<<nb, 128, SMEM_BYTES>>>(nf, pf, w000, w011, w101, w110, out);
    if (rem > 0)
        fctp_tail<<<1, 128>>>(nf, pf, w000, w011, w101, w110, out, nb * 128, n);
}

// round 4
// speedup vs baseline: 1.1119x; 1.0359x over previous
#include <cuda_runtime.h>

typedef unsigned long long ull;

__device__ __forceinline__ ull pack2(float x) {
    ull r; asm("mov.b64 %0, {%1, %1};" : "=l"(r) : "f"(x)); return r;
}
__device__ __forceinline__ void ffma2(ull &d, ull a, ull b) {
    asm("fma.rn.f32x2 %0, %1, %2, %0;" : "+l"(d) : "l"(a), "l"(b));
}
__device__ __forceinline__ void unpack2(ull v, float &lo, float &hi) {
    asm("mov.b64 {%0, %1}, %2;" : "=f"(lo), "=f"(hi) : "l"(v));
}

#define PITCH 132                     // floats per staged node row (128 + 4 pad)
#define XR_SIZE (32 * PITCH)          // per-warp staging: 32 nodes x one 32-u block
#define WSH 8192                      // weight floats (4 tensors x 2048, scaled)
#define SMEM_FLOATS (WSH + 4 * XR_SIZE)   // 8192 + 16896 = 25088
#define SMEM_BYTES  (SMEM_FLOATS * 4)     // 100352

// Thread-per-node. Weights in smem, uniform-address (broadcast) reads.
// node_feat staged per 32-u block: coalesced LDG (4 lines/instr, minimal),
// conflict-free STS.128, then per-lane LDS.128 of own row.
__global__ void __launch_bounds__(128, 2) fctp_main(
    const float* __restrict__ nf, const float* __restrict__ pf,
    const float* __restrict__ w000, const float* __restrict__ w011,
    const float* __restrict__ w101, const float* __restrict__ w110,
    float* __restrict__ out)
{
    extern __shared__ float S[];
    float* Wm = S;
    const int tid  = threadIdx.x;
    const int warp = tid >> 5, lane = tid & 31;

    // Weights scaled by 0.01*C, layout per u: [w000 16][w011 16][w110 16][w101 16]
    {
        const float c000 = 3.125e-4f;                // 0.01/32
        const float c110 = 1.8042195912175807e-4f;   // 0.01/(32*sqrt(3))
        for (int i = tid; i < 2048; i += 128) {
            int u = i >> 4, j = i & 15;
            Wm[u*64 +      j] = c000 * w000[i];
            Wm[u*64 + 16 + j] = c000 * w011[i];
            Wm[u*64 + 32 + j] = c110 * w110[i];
            Wm[u*64 + 48 + j] = c000 * w101[i];
        }
    }
    __syncthreads();

    float* XR = S + WSH + warp * XR_SIZE;
    const int nodeBase = blockIdx.x * 128 + warp * 32;
    const float4* nf4 = reinterpret_cast<const float4*>(nf) + (size_t)nodeBase * 128;

    const int nloc  = lane >> 3;   // node sub-index for coalesced LDG (0..3)
    const int piece = lane & 7;    // 16B piece within a 128B line (0..7)

    // Accumulators (v*4+w flattened into pairs): 64 ull = 128 fp32
    ull z000[8], z011[8], z110[3][8], z101[3][8];
    #pragma unroll
    for (int p = 0; p < 8; p++) {
        z000[p] = 0ull; z011[p] = 0ull;
        z110[0][p] = 0ull; z110[1][p] = 0ull; z110[2][p] = 0ull;
        z101[0][p] = 0ull; z101[1][p] = 0ull; z101[2][p] = 0ull;
    }

    const float* myrow = XR + lane * PITCH;

    for (int b = 0; b < 4; b++) {          // 4 blocks of 32 u's
        // ---- stage x0 block: 32 nodes x 128B, coalesced ----
        {
            float4 t[8];
            #pragma unroll
            for (int i = 0; i < 8; i++)
                t[i] = nf4[(size_t)(4*i + nloc) * 128 + 8*b + piece];
            #pragma unroll
            for (int i = 0; i < 8; i++)
                *reinterpret_cast<float4*>(XR + (4*i + nloc) * PITCH + 4*piece) = t[i];
        }
        // ---- stage x1 block: 32 nodes x 384B, coalesced ----
        #pragma unroll
        for (int k = 0; k < 3; k++) {
            float4 t[8];
            #pragma unroll
            for (int i = 0; i < 8; i++)
                t[i] = nf4[(size_t)(4*i + nloc) * 128 + 32 + 24*b + 8*k + piece];
            #pragma unroll
            for (int i = 0; i < 8; i++)
                *reinterpret_cast<float4*>(
                    XR + (4*i + nloc) * PITCH + 32 + 4*(8*k + piece)) = t[i];
        }
        __syncwarp();

        // ---- compute 32 u's for my node ----
        #pragma unroll
        for (int g = 0; g < 8; g++) {      // 4 u's per group
            float4 q0 = *reinterpret_cast<const float4*>(myrow + 4*g);
            float4 qa = *reinterpret_cast<const float4*>(myrow + 32 + 12*g);
            float4 qb = *reinterpret_cast<const float4*>(myrow + 32 + 12*g + 4);
            float4 qc = *reinterpret_cast<const float4*>(myrow + 32 + 12*g + 8);
            float x0s[4] = { q0.x, q0.y, q0.z, q0.w };
            float f1[12] = { qa.x, qa.y, qa.z, qa.w,
                             qb.x, qb.y, qb.z, qb.w,
                             qc.x, qc.y, qc.z, qc.w };
            #pragma unroll
            for (int j = 0; j < 4; j++) {
                const int u = 32*b + 4*g + j;
                const ulonglong2* wp =
                    reinterpret_cast<const ulonglong2*>(Wm + u * 64);
                ull xa  = pack2(x0s[j]);
                ull xb0 = pack2(f1[3*j + 0]);
                ull xb1 = pack2(f1[3*j + 1]);
                ull xb2 = pack2(f1[3*j + 2]);
                #pragma unroll
                for (int p = 0; p < 4; p++) {          // w000 (x0)
                    ulonglong2 w = wp[p];
                    ffma2(z000[2*p],   xa, w.x);
                    ffma2(z000[2*p+1], xa, w.y);
                }
                #pragma unroll
                for (int p = 0; p < 4; p++) {          // w011 (x0)
                    ulonglong2 w = wp[4 + p];
                    ffma2(z011[2*p],   xa, w.x);
                    ffma2(z011[2*p+1], xa, w.y);
                }
                #pragma unroll
                for (int p = 0; p < 4; p++) {          // w110 (x1[.,i])
                    ulonglong2 w = wp[8 + p];
                    ffma2(z110[0][2*p],   xb0, w.x);
                    ffma2(z110[0][2*p+1], xb0, w.y);
                    ffma2(z110[1][2*p],   xb1, w.x);
                    ffma2(z110[1][2*p+1], xb1, w.y);
                    ffma2(z110[2][2*p],   xb2, w.x);
                    ffma2(z110[2][2*p+1], xb2, w.y);
                }
                #pragma unroll
                for (int p = 0; p < 4; p++) {          // w101 (x1[.,k])
                    ulonglong2 w = wp[12 + p];
                    ffma2(z101[0][2*p],   xb0, w.x);
                    ffma2(z101[0][2*p+1], xb0, w.y);
                    ffma2(z101[1][2*p],   xb1, w.x);
                    ffma2(z101[1][2*p+1], xb1, w.y);
                    ffma2(z101[2][2*p],   xb2, w.x);
                    ffma2(z101[2][2*p+1], xb2, w.y);
                }
            }
        }
        __syncwarp();                      // XR reused next block
    }

    // ---------------- epilogue (registers only) ----------------
    const int node = nodeBase + lane;

    float f000[16], f011[16], f110[3][16], f101[3][16];
    #pragma unroll
    for (int p = 0; p < 8; p++) {
        unpack2(z000[p], f000[2*p], f000[2*p+1]);
        unpack2(z011[p], f011[2*p], f011[2*p+1]);
        #pragma unroll
        for (int i = 0; i < 3; i++) {
            unpack2(z110[i][p], f110[i][2*p], f110[i][2*p+1]);
            unpack2(z101[i][p], f101[i][2*p], f101[i][2*p+1]);
        }
    }

    float y[16];
    {
        const float4* p4 = reinterpret_cast<const float4*>(pf + (size_t)node * 16);
        #pragma unroll
        for (int q = 0; q < 4; q++) {
            float4 t = p4[q];
            y[4*q+0] = t.x; y[4*q+1] = t.y; y[4*q+2] = t.z; y[4*q+3] = t.w;
        }
    }

    float o0[4], o1[4][3];
    #pragma unroll
    for (int w = 0; w < 4; w++) {
        float s = 0.f, t = 0.f;
        #pragma unroll
        for (int v = 0; v < 4; v++) {
            s += f000[v*4 + w] * y[v];
            #pragma unroll
            for (int i = 0; i < 3; i++)
                t += f110[i][v*4 + w] * y[4 + 3*v + i];
        }
        o0[w] = s + t;
    }
    #pragma unroll
    for (int w = 0; w < 4; w++) {
        #pragma unroll
        for (int k = 0; k < 3; k++) {
            float s = 0.f, t = 0.f;
            #pragma unroll
            for (int v = 0; v < 4; v++) {
                s += f011[v*4 + w]    * y[4 + 3*v + k];
                t += f101[k][v*4 + w] * y[v];
            }
            o1[w][k] = s + t;
        }
    }
    o0[0] = 0.0f;   // reference zeroes out[:,0]

    float4* o4 = reinterpret_cast<float4*>(out + (size_t)node * 16);
    o4[0] = make_float4(o0[0],    o0[1],    o0[2],    o0[3]);
    o4[1] = make_float4(o1[0][0], o1[0][1], o1[0][2], o1[1][0]);
    o4[2] = make_float4(o1[1][1], o1[1][2], o1[2][0], o1[2][1]);
    o4[3] = make_float4(o1[2][2], o1[3][0], o1[3][1], o1[3][2]);
}

// naive tail kernel (only runs if n % 128 != 0; negligible work)
__global__ void fctp_tail(
    const float* __restrict__ nf, const float* __restrict__ pf,
    const float* __restrict__ w000, const float* __restrict__ w011,
    const float* __restrict__ w101, const float* __restrict__ w110,
    float* __restrict__ out, int start, int n)
{
    int node = start + blockIdx.x * blockDim.x + threadIdx.x;
    if (node >= n) return;
    const float* x = nf + (size_t)node * 512;
    const float* y = pf + (size_t)node * 16;
    float y0v[4], y1v[4][3];
    for (int v0 = 0; v0 < 4; v0++) {
        y0v[v0] = y[v0];
        for (int i = 0; i < 3; i++) y1v[v0][i] = y[4 + 3*v0 + i];
    }
    float o0[4] = {0,0,0,0}, o1[4][3] = {};
    for (int u = 0; u < 128; u++) {
        float x0u = x[u];
        float x1u[3] = { x[128 + 3*u], x[128 + 3*u + 1], x[128 + 3*u + 2] };
        for (int v0 = 0; v0 < 4; v0++) {
            float s110 = x1u[0]*y1v[v0][0] + x1u[1]*y1v[v0][1] + x1u[2]*y1v[v0][2];
            float xy0 = x0u * y0v[v0];
            for (int w = 0; w < 4; w++) {
                int idx = u*16 + v0*4 + w;
                o0[w] += 3.125e-4f * xy0 * w000[idx]
                       + 1.8042195912175807e-4f * s110 * w110[idx];
                for (int k = 0; k < 3; k++)
                    o1[w][k] += 3.125e-4f * (x0u * y1v[v0][k] * w011[idx]
                                           + x1u[k] * y0v[v0] * w101[idx]);
            }
        }
    }
    o0[0] = 0.0f;
    float* op = out + (size_t)node * 16;
    for (int w = 0; w < 4; w++) op[w] = o0[w];
    for (int w = 0; w < 4; w++)
        for (int k = 0; k < 3; k++) op[4 + 3*w + k] = o1[w][k];
}

extern "C" void kernel_launch(void* const* d_in, const int* in_sizes, int n_in,
                              void* d_out, int out_size) {
    const float* nf   = (const float*)d_in[0];
    const float* pf   = (const float*)d_in[1];
    const float* w000 = (const float*)d_in[2];
    const float* w011 = (const float*)d_in[3];
    const float* w101 = (const float*)d_in[4];
    const float* w110 = (const float*)d_in[5];
    float* out = (float*)d_out;
    int n = in_sizes[0] / 512;
    int nb  = n >> 7;
    int rem = n & 127;
    cudaFuncSetAttribute(fctp_main, cudaFuncAttributeMaxDynamicSharedMemorySize, SMEM_BYTES);
    if (nb > 0)
        fctp_main<<<nb, 128, SMEM_BYTES>>>(nf, pf, w000, w011, w101, w110, out);
    if (rem > 0)
        fctp_tail<<<1, 128>>>(nf, pf, w000, w011, w101, w110, out, nb * 128, n);
}

// round 5
// speedup vs baseline: 1.3358x; 1.2013x over previous
#include <cuda_runtime.h>
#include <cstdint>

typedef unsigned long long ull;

__device__ __forceinline__ ull pack2(float x) {
    ull r; asm("mov.b64 %0, {%1, %1};" : "=l"(r) : "f"(x)); return r;
}
__device__ __forceinline__ void ffma2(ull &d, ull a, ull b) {
    asm("fma.rn.f32x2 %0, %1, %2, %0;" : "+l"(d) : "l"(a), "l"(b));
}
__device__ __forceinline__ void unpack2(ull v, float &lo, float &hi) {
    asm("mov.b64 {%0, %1}, %2;" : "=f"(lo), "=f"(hi) : "l"(v));
}
__device__ __forceinline__ uint32_t smem_u32(const void* p) {
    uint32_t a;
    asm("{ .reg .u64 t; cvta.to.shared.u64 t, %1; cvt.u32.u64 %0, t; }"
        : "=r"(a) : "l"(p));
    return a;
}
#define CP_ASYNC16(dst, src) \
    asm volatile("cp.async.cg.shared.global [%0], [%1], 16;" :: "r"(dst), "l"(src))
#define CP_COMMIT()  asm volatile("cp.async.commit_group;" ::: "memory")
#define CP_WAIT(N)   asm volatile("cp.async.wait_group %0;" :: "n"(N) : "memory")

// XR row per node per chunk: [x0 16 floats][x1 48 floats][pad 4] = 68 floats (272B)
#define ROWF   68
#define BUFF   (32 * ROWF)            // one buffer: 32 nodes  (2176 floats)
#define XRW    (2 * BUFF)             // double-buffered per warp (4352 floats)
#define WSH    8192                   // weights: 4 tensors x 2048 (scaled)
#define SMEM_FLOATS (WSH + 4 * XRW)   // 8192 + 17408 = 25600
#define SMEM_BYTES  (SMEM_FLOATS * 4) // 102400 (x2 CTAs = 200 KB <= 228 KB)

// Stage chunk c (16 u's) of this warp's 32 nodes into XR buffer (warp-scope).
// Coalesced: instr covers 8 nodes x contiguous 64B. 16 cp.asyncs per lane total.
__device__ __forceinline__ void stage_chunk(
    uint32_t xr, const float* __restrict__ nfbase, int c, int lane)
{
    const int nl = lane >> 2, pc = lane & 3;
    #pragma unroll
    for (int i = 0; i < 4; i++) {                       // x0: 16 floats/node
        int node = 8*i + nl;
        const float* src = nfbase + (size_t)node * 512 + 16*c + 4*pc;
        CP_ASYNC16(xr + (uint32_t)(node * ROWF + 4*pc) * 4u, src);
    }
    #pragma unroll
    for (int r = 0; r < 3; r++) {                       // x1: 48 floats/node
        #pragma unroll
        for (int i = 0; i < 4; i++) {
            int node = 8*i + nl;
            int piece = 4*r + pc;
            const float* src = nfbase + (size_t)node * 512 + 128 + 48*c + 4*piece;
            CP_ASYNC16(xr + (uint32_t)(node * ROWF + 16 + 4*piece) * 4u, src);
        }
    }
}

__global__ void __launch_bounds__(128, 2) fctp_main(
    const float* __restrict__ nf, const float* __restrict__ pf,
    const float* __restrict__ w000, const float* __restrict__ w011,
    const float* __restrict__ w101, const float* __restrict__ w110,
    float* __restrict__ out)
{
    extern __shared__ float S[];
    float* Wm = S;
    const int tid  = threadIdx.x;
    const int warp = tid >> 5, lane = tid & 31;

    // Weights scaled by 0.01*C; per u: [w000 16][w011 16][w110 16][w101 16]
    {
        const float c000 = 3.125e-4f;                // 0.01/32
        const float c110 = 1.8042195912175807e-4f;   // 0.01/(32*sqrt(3))
        for (int i = tid; i < 2048; i += 128) {
            int u = i >> 4, j = i & 15;
            Wm[u*64 +      j] = c000 * w000[i];
            Wm[u*64 + 16 + j] = c000 * w011[i];
            Wm[u*64 + 32 + j] = c110 * w110[i];
            Wm[u*64 + 48 + j] = c000 * w101[i];
        }
    }
    __syncthreads();

    float* XR = S + WSH + warp * XRW;
    const uint32_t xr0 = smem_u32(XR);
    const uint32_t xr1 = xr0 + BUFF * 4u;
    const int nodeBase = blockIdx.x * 128 + warp * 32;
    const float* nfbase = nf + (size_t)nodeBase * 512;

    // Accumulators: (v*4+w) col pairs. 64 ull = 128 fp32.
    ull z000[8], z011[8], z110[3][8], z101[3][8];
    #pragma unroll
    for (int p = 0; p < 8; p++) {
        z000[p] = 0ull; z011[p] = 0ull;
        z110[0][p] = 0ull; z110[1][p] = 0ull; z110[2][p] = 0ull;
        z101[0][p] = 0ull; z101[1][p] = 0ull; z101[2][p] = 0ull;
    }

    const float* myrow0 = XR + lane * ROWF;          // buffer 0
    const float* myrow1 = myrow0 + BUFF;             // buffer 1

    stage_chunk(xr0, nfbase, 0, lane);
    CP_COMMIT();

    for (int c = 0; c < 8; c++) {                    // 8 chunks of 16 u's
        if (c < 7) {
            stage_chunk((c & 1) ? xr0 : xr1, nfbase, c + 1, lane);
            CP_COMMIT();
            CP_WAIT(1);                              // chunk c's group done
        } else {
            CP_WAIT(0);
        }
        __syncwarp();

        const float* myrow = (c & 1) ? myrow1 : myrow0;
        for (int g = 0; g < 4; g++) {                // 4 u's per group
            float4 q0 = *reinterpret_cast<const float4*>(myrow + 4*g);
            float4 qa = *reinterpret_cast<const float4*>(myrow + 16 + 12*g);
            float4 qb = *reinterpret_cast<const float4*>(myrow + 16 + 12*g + 4);
            float4 qc = *reinterpret_cast<const float4*>(myrow + 16 + 12*g + 8);
            float x0s[4] = { q0.x, q0.y, q0.z, q0.w };
            float f1[12] = { qa.x, qa.y, qa.z, qa.w,
                             qb.x, qb.y, qb.z, qb.w,
                             qc.x, qc.y, qc.z, qc.w };
            #pragma unroll
            for (int j = 0; j < 4; j++) {
                const int u = 16*c + 4*g + j;
                const ulonglong2* wp =
                    reinterpret_cast<const ulonglong2*>(Wm + u * 64);
                ull xa  = pack2(x0s[j]);
                ull xb0 = pack2(f1[3*j + 0]);
                ull xb1 = pack2(f1[3*j + 1]);
                ull xb2 = pack2(f1[3*j + 2]);
                #pragma unroll
                for (int p = 0; p < 4; p++) {        // w000 (x0)
                    ulonglong2 w = wp[p];
                    ffma2(z000[2*p],   xa, w.x);
                    ffma2(z000[2*p+1], xa, w.y);
                }
                #pragma unroll
                for (int p = 0; p < 4; p++) {        // w011 (x0)
                    ulonglong2 w = wp[4 + p];
                    ffma2(z011[2*p],   xa, w.x);
                    ffma2(z011[2*p+1], xa, w.y);
                }
                #pragma unroll
                for (int p = 0; p < 4; p++) {        // w110 (x1[.,i])
                    ulonglong2 w = wp[8 + p];
                    ffma2(z110[0][2*p],   xb0, w.x);
                    ffma2(z110[0][2*p+1], xb0, w.y);
                    ffma2(z110[1][2*p],   xb1, w.x);
                    ffma2(z110[1][2*p+1], xb1, w.y);
                    ffma2(z110[2][2*p],   xb2, w.x);
                    ffma2(z110[2][2*p+1], xb2, w.y);
                }
                #pragma unroll
                for (int p = 0; p < 4; p++) {        // w101 (x1[.,k])
                    ulonglong2 w = wp[12 + p];
                    ffma2(z101[0][2*p],   xb0, w.x);
                    ffma2(z101[0][2*p+1], xb0, w.y);
                    ffma2(z101[1][2*p],   xb1, w.x);
                    ffma2(z101[1][2*p+1], xb1, w.y);
                    ffma2(z101[2][2*p],   xb2, w.x);
                    ffma2(z101[2][2*p+1], xb2, w.y);
                }
            }
        }
        __syncwarp();   // all lanes done reading this buffer before restaging
    }

    // ---------------- epilogue (registers only) ----------------
    const int node = nodeBase + lane;

    float f000[16], f011[16], f110[3][16], f101[3][16];
    #pragma unroll
    for (int p = 0; p < 8; p++) {
        unpack2(z000[p], f000[2*p], f000[2*p+1]);
        unpack2(z011[p], f011[2*p], f011[2*p+1]);
        #pragma unroll
        for (int i = 0; i < 3; i++) {
            unpack2(z110[i][p], f110[i][2*p], f110[i][2*p+1]);
            unpack2(z101[i][p], f101[i][2*p], f101[i][2*p+1]);
        }
    }

    float y[16];
    {
        const float4* p4 = reinterpret_cast<const float4*>(pf + (size_t)node * 16);
        #pragma unroll
        for (int q = 0; q < 4; q++) {
            float4 t = p4[q];
            y[4*q+0] = t.x; y[4*q+1] = t.y; y[4*q+2] = t.z; y[4*q+3] = t.w;
        }
    }

    float o0[4], o1[4][3];
    #pragma unroll
    for (int w = 0; w < 4; w++) {
        float s = 0.f, t = 0.f;
        #pragma unroll
        for (int v = 0; v < 4; v++) {
            s += f000[v*4 + w] * y[v];
            #pragma unroll
            for (int i = 0; i < 3; i++)
                t += f110[i][v*4 + w] * y[4 + 3*v + i];
        }
        o0[w] = s + t;
    }
    #pragma unroll
    for (int w = 0; w < 4; w++) {
        #pragma unroll
        for (int k = 0; k < 3; k++) {
            float s = 0.f, t = 0.f;
            #pragma unroll
            for (int v = 0; v < 4; v++) {
                s += f011[v*4 + w]    * y[4 + 3*v + k];
                t += f101[k][v*4 + w] * y[v];
            }
            o1[w][k] = s + t;
        }
    }
    o0[0] = 0.0f;   // reference zeroes out[:,0]

    float4* o4 = reinterpret_cast<float4*>(out + (size_t)node * 16);
    o4[0] = make_float4(o0[0],    o0[1],    o0[2],    o0[3]);
    o4[1] = make_float4(o1[0][0], o1[0][1], o1[0][2], o1[1][0]);
    o4[2] = make_float4(o1[1][1], o1[1][2], o1[2][0], o1[2][1]);
    o4[3] = make_float4(o1[2][2], o1[3][0], o1[3][1], o1[3][2]);
}

// naive tail kernel (only runs if n % 128 != 0; negligible work)
__global__ void fctp_tail(
    const float* __restrict__ nf, const float* __restrict__ pf,
    const float* __restrict__ w000, const float* __restrict__ w011,
    const float* __restrict__ w101, const float* __restrict__ w110,
    float* __restrict__ out, int start, int n)
{
    int node = start + blockIdx.x * blockDim.x + threadIdx.x;
    if (node >= n) return;
    const float* x = nf + (size_t)node * 512;
    const float* y = pf + (size_t)node * 16;
    float y0v[4], y1v[4][3];
    for (int v0 = 0; v0 < 4; v0++) {
        y0v[v0] = y[v0];
        for (int i = 0; i < 3; i++) y1v[v0][i] = y[4 + 3*v0 + i];
    }
    float o0[4] = {0,0,0,0}, o1[4][3] = {};
    for (int u = 0; u < 128; u++) {
        float x0u = x[u];
        float x1u[3] = { x[128 + 3*u], x[128 + 3*u + 1], x[128 + 3*u + 2] };
        for (int v0 = 0; v0 < 4; v0++) {
            float s110 = x1u[0]*y1v[v0][0] + x1u[1]*y1v[v0][1] + x1u[2]*y1v[v0][2];
            float xy0 = x0u * y0v[v0];
            for (int w = 0; w < 4; w++) {
                int idx = u*16 + v0*4 + w;
                o0[w] += 3.125e-4f * xy0 * w000[idx]
                       + 1.8042195912175807e-4f * s110 * w110[idx];
                for (int k = 0; k < 3; k++)
                    o1[w][k] += 3.125e-4f * (x0u * y1v[v0][k] * w011[idx]
                                           + x1u[k] * y0v[v0] * w101[idx]);
            }
        }
    }
    o0[0] = 0.0f;
    float* op = out + (size_t)node * 16;
    for (int w = 0; w < 4; w++) op[w] = o0[w];
    for (int w = 0; w < 4; w++)
        for (int k = 0; k < 3; k++) op[4 + 3*w + k] = o1[w][k];
}

extern "C" void kernel_launch(void* const* d_in, const int* in_sizes, int n_in,
                              void* d_out, int out_size) {
    const float* nf   = (const float*)d_in[0];
    const float* pf   = (const float*)d_in[1];
    const float* w000 = (const float*)d_in[2];
    const float* w011 = (const float*)d_in[3];
    const float* w101 = (const float*)d_in[4];
    const float* w110 = (const float*)d_in[5];
    float* out = (float*)d_out;
    int n = in_sizes[0] / 512;
    int nb  = n >> 7;
    int rem = n & 127;
    cudaFuncSetAttribute(fctp_main, cudaFuncAttributeMaxDynamicSharedMemorySize, SMEM_BYTES);
    if (nb > 0)
        fctp_main<<<nb, 128, SMEM_BYTES>>>(nf, pf, w000, w011, w101, w110, out);
    if (rem > 0)
        fctp_tail<<<1, 128>>>(nf, pf, w000, w011, w101, w110, out, nb * 128, n);
}